// round 2
// baseline (speedup 1.0000x reference)
#include <cuda_runtime.h>
#include <cuda_bf16.h>
#include <cstdint>

// Problem shape (fixed by the bench): B=4, H=16, S=2048, D=64
#define S_LEN   2048
#define D_DIM   64
#define BH      64
#define QTILES  32   // 2048 / 64 q-rows per CTA
#define KCHUNKS 32   // 2048 / 64 k-cols per chunk

// Per-64x64-tile mask classification: 0 = all zero, 1 = mixed, 2 = all nonzero
__device__ unsigned char g_mask_flags[QTILES * KCHUNKS];

__global__ void mask_flag_kernel(const int* __restrict__ mask) {
    __shared__ int s_any_zero, s_any_nz;
    if (threadIdx.x == 0) { s_any_zero = 0; s_any_nz = 0; }
    __syncthreads();
    const int tile = blockIdx.x;
    const int qt = tile >> 5, kc = tile & 31;
    int a0 = 0, a1 = 0;
    for (int i = threadIdx.x; i < 64 * 64; i += blockDim.x) {
        int r = i >> 6, c = i & 63;
        int m = mask[(size_t)(qt * 64 + r) * S_LEN + kc * 64 + c];
        if (m == 0) a0 = 1; else a1 = 1;
    }
    if (a0) atomicOr(&s_any_zero, 1);
    if (a1) atomicOr(&s_any_nz, 1);
    __syncthreads();
    if (threadIdx.x == 0)
        g_mask_flags[tile] = (unsigned char)(s_any_zero ? (s_any_nz ? 1 : 0) : 2);
}

__device__ __forceinline__ unsigned f2tf32(float x) {
    unsigned u;
    asm("cvt.rna.tf32.f32 %0, %1;" : "=r"(u) : "f"(x));
    return u;
}

__device__ __forceinline__ void mma_tf32(float c[4], const unsigned a[4],
                                         unsigned b0, unsigned b1) {
    asm volatile(
        "mma.sync.aligned.m16n8k8.row.col.f32.tf32.tf32.f32 "
        "{%0,%1,%2,%3}, {%4,%5,%6,%7}, {%8,%9}, {%0,%1,%2,%3};"
        : "+f"(c[0]), "+f"(c[1]), "+f"(c[2]), "+f"(c[3])
        : "r"(a[0]), "r"(a[1]), "r"(a[2]), "r"(a[3]), "r"(b0), "r"(b1));
}

// 4 warps; warp w owns q-rows [16w, 16w+16) of the CTA's 64-row tile.
// m16n8k8 fragment mapping (PTX ISA):
//  A: a0(g,c) a1(g+8,c) a2(g,c+4) a3(g+8,c+4)   with g=lane>>2, c=lane&3
//  B: b0(row=c, col=g)  b1(row=c+4, col=g)
//  C: c0(g,2c) c1(g,2c+1) c2(g+8,2c) c3(g+8,2c+1)
__global__ __launch_bounds__(128)
void fused_attn_kernel(const float* __restrict__ q, const float* __restrict__ k,
                       const float* __restrict__ v, const int* __restrict__ mask,
                       float* __restrict__ out, float* __restrict__ attn,
                       int has_attn)
{
    // Padding: stride 68 -> b-frag LDS bank = 4g+tig (conflict-free)
    //          stride 72 -> V b-frag LDS bank = 8*tig+g (conflict-free)
    __shared__ float sK[64][68];   // K chunk (tf32 bits); reused as P tile in pass 2
    __shared__ float sV[64][72];   // V chunk (tf32 bits)

    const int tid  = threadIdx.x;
    const int warp = tid >> 5, lane = tid & 31;
    const int g = lane >> 2, tig = lane & 3;
    const int qtile = blockIdx.x, bh = blockIdx.y;
    const int wrow = warp * 16;

    const size_t bh_qkv = (size_t)bh * S_LEN * D_DIM;

    // --- Q fragments in registers (scaled by 1/T = 1/8, tf32), constant over chunks ---
    unsigned aq[8][4];
    {
        const float* qp = q + bh_qkv + (size_t)(qtile * 64 + wrow) * D_DIM;
        #pragma unroll
        for (int kt = 0; kt < 8; ++kt) {
            aq[kt][0] = f2tf32(qp[(size_t)(g)     * D_DIM + kt * 8 + tig]     * 0.125f);
            aq[kt][1] = f2tf32(qp[(size_t)(g + 8) * D_DIM + kt * 8 + tig]     * 0.125f);
            aq[kt][2] = f2tf32(qp[(size_t)(g)     * D_DIM + kt * 8 + tig + 4] * 0.125f);
            aq[kt][3] = f2tf32(qp[(size_t)(g + 8) * D_DIM + kt * 8 + tig + 4] * 0.125f);
        }
    }

    const int grow0 = qtile * 64 + wrow + g;  // global q row for c0/c1 (c2/c3: +8)

    float m0 = -1e30f, m1 = -1e30f, l0 = 0.f, l1 = 0.f;

    // ================= Pass 1: online row max / row sum =================
    for (int kc = 0; kc < KCHUNKS; ++kc) {
        const int flag = g_mask_flags[(qtile << 5) + kc];  // uniform across CTA
        if (flag == 0) continue;                            // fully masked: contributes nothing
        __syncthreads();
        {   // cooperative K chunk load -> smem (tf32-converted)
            const float* kp = k + bh_qkv + (size_t)kc * 64 * D_DIM;
            for (int i = tid; i < 1024; i += 128) {
                int r = i >> 4, c4 = (i & 15) << 2;
                float4 val = *(const float4*)(kp + (size_t)r * D_DIM + c4);
                float* dst = &sK[r][c4];
                dst[0] = __uint_as_float(f2tf32(val.x));
                dst[1] = __uint_as_float(f2tf32(val.y));
                dst[2] = __uint_as_float(f2tf32(val.z));
                dst[3] = __uint_as_float(f2tf32(val.w));
            }
        }
        __syncthreads();

        float c[8][4];
        #pragma unroll
        for (int nt = 0; nt < 8; ++nt) { c[nt][0] = c[nt][1] = c[nt][2] = c[nt][3] = 0.f; }
        #pragma unroll
        for (int kt = 0; kt < 8; ++kt) {
            #pragma unroll
            for (int nt = 0; nt < 8; ++nt) {
                unsigned b0 = __float_as_uint(sK[nt * 8 + g][kt * 8 + tig]);
                unsigned b1 = __float_as_uint(sK[nt * 8 + g][kt * 8 + tig + 4]);
                mma_tf32(c[nt], aq[kt], b0, b1);
            }
        }
        // abs() BEFORE masking (matches reference)
        #pragma unroll
        for (int nt = 0; nt < 8; ++nt) {
            c[nt][0] = fabsf(c[nt][0]); c[nt][1] = fabsf(c[nt][1]);
            c[nt][2] = fabsf(c[nt][2]); c[nt][3] = fabsf(c[nt][3]);
        }
        if (flag == 1) {
            #pragma unroll
            for (int nt = 0; nt < 8; ++nt) {
                int col = kc * 64 + nt * 8 + 2 * tig;
                int2 mv0 = *(const int2*)(mask + (size_t)grow0 * S_LEN + col);
                int2 mv1 = *(const int2*)(mask + (size_t)(grow0 + 8) * S_LEN + col);
                if (mv0.x == 0) c[nt][0] = -1e9f;
                if (mv0.y == 0) c[nt][1] = -1e9f;
                if (mv1.x == 0) c[nt][2] = -1e9f;
                if (mv1.y == 0) c[nt][3] = -1e9f;
            }
        }
        // chunk row max (quad reduce: lanes with equal lane>>2 share rows)
        float cm0 = -1e30f, cm1 = -1e30f;
        #pragma unroll
        for (int nt = 0; nt < 8; ++nt) {
            cm0 = fmaxf(cm0, fmaxf(c[nt][0], c[nt][1]));
            cm1 = fmaxf(cm1, fmaxf(c[nt][2], c[nt][3]));
        }
        cm0 = fmaxf(cm0, __shfl_xor_sync(0xffffffffu, cm0, 1));
        cm0 = fmaxf(cm0, __shfl_xor_sync(0xffffffffu, cm0, 2));
        cm1 = fmaxf(cm1, __shfl_xor_sync(0xffffffffu, cm1, 1));
        cm1 = fmaxf(cm1, __shfl_xor_sync(0xffffffffu, cm1, 2));
        float nm0 = fmaxf(m0, cm0), nm1 = fmaxf(m1, cm1);
        float s0 = 0.f, s1 = 0.f;
        #pragma unroll
        for (int nt = 0; nt < 8; ++nt) {
            s0 += __expf(c[nt][0] - nm0) + __expf(c[nt][1] - nm0);
            s1 += __expf(c[nt][2] - nm1) + __expf(c[nt][3] - nm1);
        }
        s0 += __shfl_xor_sync(0xffffffffu, s0, 1);
        s0 += __shfl_xor_sync(0xffffffffu, s0, 2);
        s1 += __shfl_xor_sync(0xffffffffu, s1, 1);
        s1 += __shfl_xor_sync(0xffffffffu, s1, 2);
        l0 = l0 * __expf(m0 - nm0) + s0;  m0 = nm0;
        l1 = l1 * __expf(m1 - nm1) + s1;  m1 = nm1;
    }

    const float il0 = 1.f / l0, il1 = 1.f / l1;

    // ================= Pass 2: attn write + O = P @ V =================
    float o[8][4];
    #pragma unroll
    for (int nt = 0; nt < 8; ++nt) { o[nt][0] = o[nt][1] = o[nt][2] = o[nt][3] = 0.f; }

    for (int kc = 0; kc < KCHUNKS; ++kc) {
        const int flag = g_mask_flags[(qtile << 5) + kc];
        float* ap0 = has_attn
            ? attn + (size_t)bh * S_LEN * S_LEN + (size_t)grow0 * S_LEN + kc * 64
            : nullptr;
        if (flag == 0) {   // masked tile: attn = 0, no O contribution
            if (has_attn) {
                float2 z = make_float2(0.f, 0.f);
                #pragma unroll
                for (int nt = 0; nt < 8; ++nt) {
                    *(float2*)(ap0 + nt * 8 + 2 * tig) = z;
                    *(float2*)(ap0 + (size_t)8 * S_LEN + nt * 8 + 2 * tig) = z;
                }
            }
            continue;
        }
        __syncthreads();   // previous chunk fully consumed (sK as P, sV)
        {   // cooperative K + V chunk loads (tf32-converted)
            const float* kp = k + bh_qkv + (size_t)kc * 64 * D_DIM;
            const float* vp = v + bh_qkv + (size_t)kc * 64 * D_DIM;
            for (int i = tid; i < 1024; i += 128) {
                int r = i >> 4, c4 = (i & 15) << 2;
                float4 kvv = *(const float4*)(kp + (size_t)r * D_DIM + c4);
                float* dk = &sK[r][c4];
                dk[0] = __uint_as_float(f2tf32(kvv.x));
                dk[1] = __uint_as_float(f2tf32(kvv.y));
                dk[2] = __uint_as_float(f2tf32(kvv.z));
                dk[3] = __uint_as_float(f2tf32(kvv.w));
                float4 vvv = *(const float4*)(vp + (size_t)r * D_DIM + c4);
                float* dv = &sV[r][c4];
                dv[0] = __uint_as_float(f2tf32(vvv.x));
                dv[1] = __uint_as_float(f2tf32(vvv.y));
                dv[2] = __uint_as_float(f2tf32(vvv.z));
                dv[3] = __uint_as_float(f2tf32(vvv.w));
            }
        }
        __syncthreads();

        // Recompute scores
        float c[8][4];
        #pragma unroll
        for (int nt = 0; nt < 8; ++nt) { c[nt][0] = c[nt][1] = c[nt][2] = c[nt][3] = 0.f; }
        #pragma unroll
        for (int kt = 0; kt < 8; ++kt) {
            #pragma unroll
            for (int nt = 0; nt < 8; ++nt) {
                unsigned b0 = __float_as_uint(sK[nt * 8 + g][kt * 8 + tig]);
                unsigned b1 = __float_as_uint(sK[nt * 8 + g][kt * 8 + tig + 4]);
                mma_tf32(c[nt], aq[kt], b0, b1);
            }
        }
        #pragma unroll
        for (int nt = 0; nt < 8; ++nt) {
            c[nt][0] = fabsf(c[nt][0]); c[nt][1] = fabsf(c[nt][1]);
            c[nt][2] = fabsf(c[nt][2]); c[nt][3] = fabsf(c[nt][3]);
        }
        if (flag == 1) {
            #pragma unroll
            for (int nt = 0; nt < 8; ++nt) {
                int col = kc * 64 + nt * 8 + 2 * tig;
                int2 mv0 = *(const int2*)(mask + (size_t)grow0 * S_LEN + col);
                int2 mv1 = *(const int2*)(mask + (size_t)(grow0 + 8) * S_LEN + col);
                if (mv0.x == 0) c[nt][0] = -1e9f;
                if (mv0.y == 0) c[nt][1] = -1e9f;
                if (mv1.x == 0) c[nt][2] = -1e9f;
                if (mv1.y == 0) c[nt][3] = -1e9f;
            }
        }
        // Final normalized probabilities
        #pragma unroll
        for (int nt = 0; nt < 8; ++nt) {
            c[nt][0] = __expf(c[nt][0] - m0) * il0;
            c[nt][1] = __expf(c[nt][1] - m0) * il0;
            c[nt][2] = __expf(c[nt][2] - m1) * il1;
            c[nt][3] = __expf(c[nt][3] - m1) * il1;
        }

        __syncthreads();   // all warps done reading sK (K) before P overwrites it

        // attn store (fp32) + P tile into sK (tf32). Each warp writes/reads ONLY
        // its own 16 rows of sK here, so __syncwarp suffices after the store.
        #pragma unroll
        for (int nt = 0; nt < 8; ++nt) {
            int colb = nt * 8 + 2 * tig;
            if (has_attn) {
                *(float2*)(ap0 + colb) = make_float2(c[nt][0], c[nt][1]);
                *(float2*)(ap0 + (size_t)8 * S_LEN + colb) = make_float2(c[nt][2], c[nt][3]);
            }
            sK[wrow + g][colb]         = __uint_as_float(f2tf32(c[nt][0]));
            sK[wrow + g][colb + 1]     = __uint_as_float(f2tf32(c[nt][1]));
            sK[wrow + g + 8][colb]     = __uint_as_float(f2tf32(c[nt][2]));
            sK[wrow + g + 8][colb + 1] = __uint_as_float(f2tf32(c[nt][3]));
        }
        __syncwarp();

        // O += P @ V
        #pragma unroll
        for (int kt = 0; kt < 8; ++kt) {
            unsigned pa[4];
            pa[0] = __float_as_uint(sK[wrow + g]    [kt * 8 + tig]);
            pa[1] = __float_as_uint(sK[wrow + g + 8][kt * 8 + tig]);
            pa[2] = __float_as_uint(sK[wrow + g]    [kt * 8 + tig + 4]);
            pa[3] = __float_as_uint(sK[wrow + g + 8][kt * 8 + tig + 4]);
            #pragma unroll
            for (int nt = 0; nt < 8; ++nt) {
                unsigned b0 = __float_as_uint(sV[kt * 8 + tig]    [nt * 8 + g]);
                unsigned b1 = __float_as_uint(sV[kt * 8 + tig + 4][nt * 8 + g]);
                mma_tf32(o[nt], pa, b0, b1);
            }
        }
    }

    // ================= Output store =================
    {
        float* op0 = out + bh_qkv + (size_t)grow0 * D_DIM;
        float* op1 = out + bh_qkv + (size_t)(grow0 + 8) * D_DIM;
        #pragma unroll
        for (int nt = 0; nt < 8; ++nt) {
            *(float2*)(op0 + nt * 8 + 2 * tig) = make_float2(o[nt][0], o[nt][1]);
            *(float2*)(op1 + nt * 8 + 2 * tig) = make_float2(o[nt][2], o[nt][3]);
        }
    }
}

extern "C" void kernel_launch(void* const* d_in, const int* in_sizes, int n_in,
                              void* d_out, int out_size) {
    const float* q    = (const float*)d_in[0];
    const float* k    = (const float*)d_in[1];
    const float* v    = (const float*)d_in[2];
    const int*   mask = (const int*)d_in[3];

    float* out = (float*)d_out;
    const long long outN  = (long long)BH * S_LEN * D_DIM;   // 8,388,608
    const long long attnN = (long long)BH * S_LEN * S_LEN;   // 268,435,456
    float* attn = nullptr;
    int has_attn = 0;
    if ((long long)out_size >= outN + attnN) {   // tuple (out, attn) flattened
        attn = out + outN;
        has_attn = 1;
    }

    mask_flag_kernel<<<QTILES * KCHUNKS, 256>>>(mask);
    dim3 grid(QTILES, BH);
    fused_attn_kernel<<<grid, 128>>>(q, k, v, mask, out, attn, has_attn);
}

// round 3
// speedup vs baseline: 1.0021x; 1.0021x over previous
#include <cuda_runtime.h>
#include <cuda_bf16.h>
#include <cstdint>

// Problem shape (fixed by the bench): B=4, H=16, S=2048, D=64
#define S_LEN   2048
#define D_DIM   64
#define BH      64
#define QTILES  32   // 2048 / 64 q-rows per CTA
#define KCHUNKS 32   // 2048 / 64 k-cols per chunk

// Per-64x64-tile mask classification: 0 = all zero, 1 = mixed, 2 = all nonzero
__device__ unsigned char g_mask_flags[QTILES * KCHUNKS];

__global__ void mask_flag_kernel(const int* __restrict__ mask) {
    __shared__ int s_any_zero, s_any_nz;
    if (threadIdx.x == 0) { s_any_zero = 0; s_any_nz = 0; }
    __syncthreads();
    const int tile = blockIdx.x;
    const int qt = tile >> 5, kc = tile & 31;
    int a0 = 0, a1 = 0;
    for (int i = threadIdx.x; i < 64 * 64; i += blockDim.x) {
        int r = i >> 6, c = i & 63;
        int m = mask[(size_t)(qt * 64 + r) * S_LEN + kc * 64 + c];
        if (m == 0) a0 = 1; else a1 = 1;
    }
    if (a0) atomicOr(&s_any_zero, 1);
    if (a1) atomicOr(&s_any_nz, 1);
    __syncthreads();
    if (threadIdx.x == 0)
        g_mask_flags[tile] = (unsigned char)(s_any_zero ? (s_any_nz ? 1 : 0) : 2);
}

__device__ __forceinline__ unsigned f2tf32(float x) {
    unsigned u;
    asm("cvt.rna.tf32.f32 %0, %1;" : "=r"(u) : "f"(x));
    return u;
}

__device__ __forceinline__ void mma_tf32(float c[4], const unsigned a[4],
                                         unsigned b0, unsigned b1) {
    asm volatile(
        "mma.sync.aligned.m16n8k8.row.col.f32.tf32.tf32.f32 "
        "{%0,%1,%2,%3}, {%4,%5,%6,%7}, {%8,%9}, {%0,%1,%2,%3};"
        : "+f"(c[0]), "+f"(c[1]), "+f"(c[2]), "+f"(c[3])
        : "r"(a[0]), "r"(a[1]), "r"(a[2]), "r"(a[3]), "r"(b0), "r"(b1));
}

// 4 warps; warp w owns q-rows [16w, 16w+16) of the CTA's 64-row tile.
// m16n8k8 fragment mapping (PTX ISA):
//  A: a0(g,c) a1(g+8,c) a2(g,c+4) a3(g+8,c+4)   with g=lane>>2, c=lane&3
//  B: b0(row=c, col=g)  b1(row=c+4, col=g)
//  C: c0(g,2c) c1(g,2c+1) c2(g+8,2c) c3(g+8,2c+1)
__global__ __launch_bounds__(128)
void fused_attn_kernel(const float* __restrict__ q, const float* __restrict__ k,
                       const float* __restrict__ v, const int* __restrict__ mask,
                       float* __restrict__ out, float* __restrict__ attn,
                       int has_attn)
{
    // Padding: stride 68 -> b-frag LDS bank = 4g+tig (conflict-free)
    //          stride 72 -> V b-frag LDS bank = 8*tig+g (conflict-free)
    __shared__ float sK[64][68];   // K chunk (tf32 bits); reused as P tile in pass 2
    __shared__ float sV[64][72];   // V chunk (tf32 bits)

    const int tid  = threadIdx.x;
    const int warp = tid >> 5, lane = tid & 31;
    const int g = lane >> 2, tig = lane & 3;
    const int qtile = blockIdx.x, bh = blockIdx.y;
    const int wrow = warp * 16;

    const size_t bh_qkv = (size_t)bh * S_LEN * D_DIM;

    // --- Q fragments in registers (scaled by 1/T = 1/8, tf32), constant over chunks ---
    unsigned aq[8][4];
    {
        const float* qp = q + bh_qkv + (size_t)(qtile * 64 + wrow) * D_DIM;
        #pragma unroll
        for (int kt = 0; kt < 8; ++kt) {
            aq[kt][0] = f2tf32(qp[(size_t)(g)     * D_DIM + kt * 8 + tig]     * 0.125f);
            aq[kt][1] = f2tf32(qp[(size_t)(g + 8) * D_DIM + kt * 8 + tig]     * 0.125f);
            aq[kt][2] = f2tf32(qp[(size_t)(g)     * D_DIM + kt * 8 + tig + 4] * 0.125f);
            aq[kt][3] = f2tf32(qp[(size_t)(g + 8) * D_DIM + kt * 8 + tig + 4] * 0.125f);
        }
    }

    const int grow0 = qtile * 64 + wrow + g;  // global q row for c0/c1 (c2/c3: +8)

    float m0 = -1e30f, m1 = -1e30f, l0 = 0.f, l1 = 0.f;

    // ================= Pass 1: online row max / row sum =================
    for (int kc = 0; kc < KCHUNKS; ++kc) {
        const int flag = g_mask_flags[(qtile << 5) + kc];  // uniform across CTA
        if (flag == 0) continue;                            // fully masked: contributes nothing
        __syncthreads();
        {   // cooperative K chunk load -> smem (tf32-converted)
            const float* kp = k + bh_qkv + (size_t)kc * 64 * D_DIM;
            for (int i = tid; i < 1024; i += 128) {
                int r = i >> 4, c4 = (i & 15) << 2;
                float4 val = *(const float4*)(kp + (size_t)r * D_DIM + c4);
                float* dst = &sK[r][c4];
                dst[0] = __uint_as_float(f2tf32(val.x));
                dst[1] = __uint_as_float(f2tf32(val.y));
                dst[2] = __uint_as_float(f2tf32(val.z));
                dst[3] = __uint_as_float(f2tf32(val.w));
            }
        }
        __syncthreads();

        float c[8][4];
        #pragma unroll
        for (int nt = 0; nt < 8; ++nt) { c[nt][0] = c[nt][1] = c[nt][2] = c[nt][3] = 0.f; }
        #pragma unroll
        for (int kt = 0; kt < 8; ++kt) {
            #pragma unroll
            for (int nt = 0; nt < 8; ++nt) {
                unsigned b0 = __float_as_uint(sK[nt * 8 + g][kt * 8 + tig]);
                unsigned b1 = __float_as_uint(sK[nt * 8 + g][kt * 8 + tig + 4]);
                mma_tf32(c[nt], aq[kt], b0, b1);
            }
        }
        // abs() BEFORE masking (matches reference)
        #pragma unroll
        for (int nt = 0; nt < 8; ++nt) {
            c[nt][0] = fabsf(c[nt][0]); c[nt][1] = fabsf(c[nt][1]);
            c[nt][2] = fabsf(c[nt][2]); c[nt][3] = fabsf(c[nt][3]);
        }
        if (flag == 1) {
            #pragma unroll
            for (int nt = 0; nt < 8; ++nt) {
                int col = kc * 64 + nt * 8 + 2 * tig;
                int2 mv0 = *(const int2*)(mask + (size_t)grow0 * S_LEN + col);
                int2 mv1 = *(const int2*)(mask + (size_t)(grow0 + 8) * S_LEN + col);
                if (mv0.x == 0) c[nt][0] = -1e9f;
                if (mv0.y == 0) c[nt][1] = -1e9f;
                if (mv1.x == 0) c[nt][2] = -1e9f;
                if (mv1.y == 0) c[nt][3] = -1e9f;
            }
        }
        // chunk row max (quad reduce: lanes with equal lane>>2 share rows)
        float cm0 = -1e30f, cm1 = -1e30f;
        #pragma unroll
        for (int nt = 0; nt < 8; ++nt) {
            cm0 = fmaxf(cm0, fmaxf(c[nt][0], c[nt][1]));
            cm1 = fmaxf(cm1, fmaxf(c[nt][2], c[nt][3]));
        }
        cm0 = fmaxf(cm0, __shfl_xor_sync(0xffffffffu, cm0, 1));
        cm0 = fmaxf(cm0, __shfl_xor_sync(0xffffffffu, cm0, 2));
        cm1 = fmaxf(cm1, __shfl_xor_sync(0xffffffffu, cm1, 1));
        cm1 = fmaxf(cm1, __shfl_xor_sync(0xffffffffu, cm1, 2));
        float nm0 = fmaxf(m0, cm0), nm1 = fmaxf(m1, cm1);
        float s0 = 0.f, s1 = 0.f;
        #pragma unroll
        for (int nt = 0; nt < 8; ++nt) {
            s0 += __expf(c[nt][0] - nm0) + __expf(c[nt][1] - nm0);
            s1 += __expf(c[nt][2] - nm1) + __expf(c[nt][3] - nm1);
        }
        s0 += __shfl_xor_sync(0xffffffffu, s0, 1);
        s0 += __shfl_xor_sync(0xffffffffu, s0, 2);
        s1 += __shfl_xor_sync(0xffffffffu, s1, 1);
        s1 += __shfl_xor_sync(0xffffffffu, s1, 2);
        l0 = l0 * __expf(m0 - nm0) + s0;  m0 = nm0;
        l1 = l1 * __expf(m1 - nm1) + s1;  m1 = nm1;
    }

    const float il0 = 1.f / l0, il1 = 1.f / l1;

    // ================= Pass 2: attn write + O = P @ V =================
    float o[8][4];
    #pragma unroll
    for (int nt = 0; nt < 8; ++nt) { o[nt][0] = o[nt][1] = o[nt][2] = o[nt][3] = 0.f; }

    for (int kc = 0; kc < KCHUNKS; ++kc) {
        const int flag = g_mask_flags[(qtile << 5) + kc];
        float* ap0 = has_attn
            ? attn + (size_t)bh * S_LEN * S_LEN + (size_t)grow0 * S_LEN + kc * 64
            : nullptr;
        if (flag == 0) {   // masked tile: attn = 0, no O contribution
            if (has_attn) {
                float2 z = make_float2(0.f, 0.f);
                #pragma unroll
                for (int nt = 0; nt < 8; ++nt) {
                    *(float2*)(ap0 + nt * 8 + 2 * tig) = z;
                    *(float2*)(ap0 + (size_t)8 * S_LEN + nt * 8 + 2 * tig) = z;
                }
            }
            continue;
        }
        __syncthreads();   // previous chunk fully consumed (sK as P, sV)
        {   // cooperative K + V chunk loads (tf32-converted)
            const float* kp = k + bh_qkv + (size_t)kc * 64 * D_DIM;
            const float* vp = v + bh_qkv + (size_t)kc * 64 * D_DIM;
            for (int i = tid; i < 1024; i += 128) {
                int r = i >> 4, c4 = (i & 15) << 2;
                float4 kvv = *(const float4*)(kp + (size_t)r * D_DIM + c4);
                float* dk = &sK[r][c4];
                dk[0] = __uint_as_float(f2tf32(kvv.x));
                dk[1] = __uint_as_float(f2tf32(kvv.y));
                dk[2] = __uint_as_float(f2tf32(kvv.z));
                dk[3] = __uint_as_float(f2tf32(kvv.w));
                float4 vvv = *(const float4*)(vp + (size_t)r * D_DIM + c4);
                float* dv = &sV[r][c4];
                dv[0] = __uint_as_float(f2tf32(vvv.x));
                dv[1] = __uint_as_float(f2tf32(vvv.y));
                dv[2] = __uint_as_float(f2tf32(vvv.z));
                dv[3] = __uint_as_float(f2tf32(vvv.w));
            }
        }
        __syncthreads();

        // Recompute scores
        float c[8][4];
        #pragma unroll
        for (int nt = 0; nt < 8; ++nt) { c[nt][0] = c[nt][1] = c[nt][2] = c[nt][3] = 0.f; }
        #pragma unroll
        for (int kt = 0; kt < 8; ++kt) {
            #pragma unroll
            for (int nt = 0; nt < 8; ++nt) {
                unsigned b0 = __float_as_uint(sK[nt * 8 + g][kt * 8 + tig]);
                unsigned b1 = __float_as_uint(sK[nt * 8 + g][kt * 8 + tig + 4]);
                mma_tf32(c[nt], aq[kt], b0, b1);
            }
        }
        #pragma unroll
        for (int nt = 0; nt < 8; ++nt) {
            c[nt][0] = fabsf(c[nt][0]); c[nt][1] = fabsf(c[nt][1]);
            c[nt][2] = fabsf(c[nt][2]); c[nt][3] = fabsf(c[nt][3]);
        }
        if (flag == 1) {
            #pragma unroll
            for (int nt = 0; nt < 8; ++nt) {
                int col = kc * 64 + nt * 8 + 2 * tig;
                int2 mv0 = *(const int2*)(mask + (size_t)grow0 * S_LEN + col);
                int2 mv1 = *(const int2*)(mask + (size_t)(grow0 + 8) * S_LEN + col);
                if (mv0.x == 0) c[nt][0] = -1e9f;
                if (mv0.y == 0) c[nt][1] = -1e9f;
                if (mv1.x == 0) c[nt][2] = -1e9f;
                if (mv1.y == 0) c[nt][3] = -1e9f;
            }
        }
        // Final normalized probabilities
        #pragma unroll
        for (int nt = 0; nt < 8; ++nt) {
            c[nt][0] = __expf(c[nt][0] - m0) * il0;
            c[nt][1] = __expf(c[nt][1] - m0) * il0;
            c[nt][2] = __expf(c[nt][2] - m1) * il1;
            c[nt][3] = __expf(c[nt][3] - m1) * il1;
        }

        __syncthreads();   // all warps done reading sK (K) before P overwrites it

        // attn store (fp32) + P tile into sK (tf32). Each warp writes/reads ONLY
        // its own 16 rows of sK here, so __syncwarp suffices after the store.
        #pragma unroll
        for (int nt = 0; nt < 8; ++nt) {
            int colb = nt * 8 + 2 * tig;
            if (has_attn) {
                *(float2*)(ap0 + colb) = make_float2(c[nt][0], c[nt][1]);
                *(float2*)(ap0 + (size_t)8 * S_LEN + colb) = make_float2(c[nt][2], c[nt][3]);
            }
            sK[wrow + g][colb]         = __uint_as_float(f2tf32(c[nt][0]));
            sK[wrow + g][colb + 1]     = __uint_as_float(f2tf32(c[nt][1]));
            sK[wrow + g + 8][colb]     = __uint_as_float(f2tf32(c[nt][2]));
            sK[wrow + g + 8][colb + 1] = __uint_as_float(f2tf32(c[nt][3]));
        }
        __syncwarp();

        // O += P @ V
        #pragma unroll
        for (int kt = 0; kt < 8; ++kt) {
            unsigned pa[4];
            pa[0] = __float_as_uint(sK[wrow + g]    [kt * 8 + tig]);
            pa[1] = __float_as_uint(sK[wrow + g + 8][kt * 8 + tig]);
            pa[2] = __float_as_uint(sK[wrow + g]    [kt * 8 + tig + 4]);
            pa[3] = __float_as_uint(sK[wrow + g + 8][kt * 8 + tig + 4]);
            #pragma unroll
            for (int nt = 0; nt < 8; ++nt) {
                unsigned b0 = __float_as_uint(sV[kt * 8 + tig]    [nt * 8 + g]);
                unsigned b1 = __float_as_uint(sV[kt * 8 + tig + 4][nt * 8 + g]);
                mma_tf32(o[nt], pa, b0, b1);
            }
        }
    }

    // ================= Output store =================
    {
        float* op0 = out + bh_qkv + (size_t)grow0 * D_DIM;
        float* op1 = out + bh_qkv + (size_t)(grow0 + 8) * D_DIM;
        #pragma unroll
        for (int nt = 0; nt < 8; ++nt) {
            *(float2*)(op0 + nt * 8 + 2 * tig) = make_float2(o[nt][0], o[nt][1]);
            *(float2*)(op1 + nt * 8 + 2 * tig) = make_float2(o[nt][2], o[nt][3]);
        }
    }
}

extern "C" void kernel_launch(void* const* d_in, const int* in_sizes, int n_in,
                              void* d_out, int out_size) {
    const float* q    = (const float*)d_in[0];
    const float* k    = (const float*)d_in[1];
    const float* v    = (const float*)d_in[2];
    const int*   mask = (const int*)d_in[3];

    float* out = (float*)d_out;
    const long long outN  = (long long)BH * S_LEN * D_DIM;   // 8,388,608
    const long long attnN = (long long)BH * S_LEN * S_LEN;   // 268,435,456
    float* attn = nullptr;
    int has_attn = 0;
    if ((long long)out_size >= outN + attnN) {   // tuple (out, attn) flattened
        attn = out + outN;
        has_attn = 1;
    }

    mask_flag_kernel<<<QTILES * KCHUNKS, 256>>>(mask);
    dim3 grid(QTILES, BH);
    fused_attn_kernel<<<grid, 128>>>(q, k, v, mask, out, attn, has_attn);
}

// round 5
// speedup vs baseline: 1.1914x; 1.1889x over previous
#include <cuda_runtime.h>
#include <cstdint>

// Shape fixed by the bench: B=4, H=16, S=2048, D=64
#define S_LEN 2048
#define D_DIM 64
#define BH    64
#define QT    128               // q rows per CTA (4 warps x 32 rows)
#define NQT   (S_LEN / QT)      // 16
#define NKC   (S_LEN / 64)      // 32 k-chunks of 64

// ---------------- mask tile classification (64x64 tiles) ----------------
__device__ unsigned char g_mask_flags[32 * 32]; // [qt64][kc]: 0 all-zero, 1 mixed, 2 all-nonzero

__global__ void mask_flag_kernel(const int* __restrict__ mask) {
    __shared__ int s_any_zero, s_any_nz;
    if (threadIdx.x == 0) { s_any_zero = 0; s_any_nz = 0; }
    __syncthreads();
    const int tile = blockIdx.x;
    const int qt = tile >> 5, kc = tile & 31;
    int a0 = 0, a1 = 0;
    for (int i = threadIdx.x; i < 64 * 64; i += blockDim.x) {
        int r = i >> 6, c = i & 63;
        int m = mask[(size_t)(qt * 64 + r) * S_LEN + kc * 64 + c];
        if (m == 0) a0 = 1; else a1 = 1;
    }
    if (a0) atomicOr(&s_any_zero, 1);
    if (a1) atomicOr(&s_any_nz, 1);
    __syncthreads();
    if (threadIdx.x == 0)
        g_mask_flags[tile] = (unsigned char)(s_any_zero ? (s_any_nz ? 1 : 0) : 2);
}

__device__ __forceinline__ unsigned f2tf32(float x) {
    unsigned u; asm("cvt.rna.tf32.f32 %0, %1;" : "=r"(u) : "f"(x)); return u;
}

__device__ __forceinline__ void mma_tf32(float* c, const unsigned* a,
                                         unsigned b0, unsigned b1) {
    asm volatile(
        "mma.sync.aligned.m16n8k8.row.col.f32.tf32.tf32.f32 "
        "{%0,%1,%2,%3}, {%4,%5,%6,%7}, {%8,%9}, {%0,%1,%2,%3};"
        : "+f"(c[0]), "+f"(c[1]), "+f"(c[2]), "+f"(c[3])
        : "r"(a[0]), "r"(a[1]), "r"(a[2]), "r"(a[3]), "r"(b0), "r"(b1));
}

// Smem layout (floats). Strides chosen for conflict-free b/a-fragment LDS:
//   stride 68: bank(4g+tig) pattern; stride 72: bank(8tig+g) pattern.
#define SKS 68
#define SVS 72
#define SPS 68
#define OFF_K 0
#define OFF_V (64 * SKS)                // 4352
#define OFF_P (64 * SKS + 64 * SVS)     // 8960
#define SMEM_FLOATS (OFF_P + 128 * SPS) // 17664 floats = 70656 B

// m16n8k8 frag mapping: A a0(g,c) a1(g+8,c) a2(g,c+4) a3(g+8,c+4), g=lane>>2, c=lane&3
//                       B b0(row=c,col=g) b1(row=c+4,col=g)
//                       C c0(g,2c) c1(g,2c+1) c2(g+8,2c) c3(g+8,2c+1)
__global__ __launch_bounds__(128)
void fused_attn2_kernel(const float* __restrict__ q, const float* __restrict__ k,
                        const float* __restrict__ v, const int* __restrict__ mask,
                        float* __restrict__ out, float* __restrict__ attn,
                        int has_attn)
{
    extern __shared__ float sm[];
    float* sK = sm + OFF_K;   // [64][68]  K chunk (tf32 bits)
    float* sV = sm + OFF_V;   // [64][72]  V chunk (tf32 bits)
    float* sP = sm + OFF_P;   // [128][68] P tile  (tf32 bits)

    const int tid = threadIdx.x;
    const int warp = tid >> 5, lane = tid & 31;
    const int g = lane >> 2, tig = lane & 3;
    const int qtile = blockIdx.x, bh = blockIdx.y;
    const int wrow = warp * 32;
    const size_t bh_qkv = (size_t)bh * S_LEN * D_DIM;
    const int gq = qtile * QT + wrow;          // warp's first global q row

    // ---- Q a-fragments in registers (scaled by 1/8, RNA tf32); 2 m-tiles ----
    unsigned aq[2][8][4];
    {
        const float* qp = q + bh_qkv + (size_t)gq * D_DIM;
        #pragma unroll
        for (int t = 0; t < 2; ++t)
            #pragma unroll
            for (int kt = 0; kt < 8; ++kt) {
                const float* r0 = qp + (size_t)(t * 16 + g) * D_DIM + kt * 8;
                const float* r1 = r0 + 8 * D_DIM;
                aq[t][kt][0] = f2tf32(r0[tig]     * 0.125f);
                aq[t][kt][1] = f2tf32(r1[tig]     * 0.125f);
                aq[t][kt][2] = f2tf32(r0[tig + 4] * 0.125f);
                aq[t][kt][3] = f2tf32(r1[tig + 4] * 0.125f);
            }
    }

    const int fb0 = (qtile * 2) * 32, fb1 = (qtile * 2 + 1) * 32;

    // ================= Pass 1: row sums l = sum exp(|s| masked) =================
    float l00 = 0.f, l01 = 0.f, l10 = 0.f, l11 = 0.f;
    for (int kc = 0; kc < NKC; ++kc) {
        const int cf0 = g_mask_flags[fb0 + kc], cf1 = g_mask_flags[fb1 + kc];
        if (cf0 == 0 && cf1 == 0) continue;
        __syncthreads();
        {   // K chunk fill
            const float* kp = k + bh_qkv + (size_t)kc * 64 * D_DIM;
            for (int i = tid; i < 1024; i += 128) {
                int r = i >> 4, c4 = (i & 15) << 2;
                float4 val = *(const float4*)(kp + (size_t)r * D_DIM + c4);
                *(float4*)(&sK[r * SKS + c4]) = make_float4(
                    __uint_as_float(f2tf32(val.x)), __uint_as_float(f2tf32(val.y)),
                    __uint_as_float(f2tf32(val.z)), __uint_as_float(f2tf32(val.w)));
            }
        }
        __syncthreads();

        float C0[8][4], C1[8][4];
        #pragma unroll
        for (int nt = 0; nt < 8; ++nt)
            #pragma unroll
            for (int i = 0; i < 4; ++i) { C0[nt][i] = 0.f; C1[nt][i] = 0.f; }
        #pragma unroll
        for (int kt = 0; kt < 8; ++kt)
            #pragma unroll
            for (int nt = 0; nt < 8; ++nt) {
                unsigned b0 = __float_as_uint(sK[(nt * 8 + g) * SKS + kt * 8 + tig]);
                unsigned b1 = __float_as_uint(sK[(nt * 8 + g) * SKS + kt * 8 + tig + 4]);
                mma_tf32(C0[nt], aq[0][kt], b0, b1);   // b-frag reused for both m-tiles
                mma_tf32(C1[nt], aq[1][kt], b0, b1);
            }

        const int wflag = (warp < 2) ? cf0 : cf1;
        if (wflag == 2) {
            #pragma unroll
            for (int nt = 0; nt < 8; ++nt) {
                l00 += __expf(fabsf(C0[nt][0])) + __expf(fabsf(C0[nt][1]));
                l01 += __expf(fabsf(C0[nt][2])) + __expf(fabsf(C0[nt][3]));
                l10 += __expf(fabsf(C1[nt][0])) + __expf(fabsf(C1[nt][1]));
                l11 += __expf(fabsf(C1[nt][2])) + __expf(fabsf(C1[nt][3]));
            }
        } else {
            const int colb = kc * 64 + 2 * tig;
            #pragma unroll
            for (int nt = 0; nt < 8; ++nt) {
                int2 mA = *(const int2*)(mask + (size_t)(gq + g)      * S_LEN + colb + nt * 8);
                int2 mB = *(const int2*)(mask + (size_t)(gq + g + 8)  * S_LEN + colb + nt * 8);
                int2 mC = *(const int2*)(mask + (size_t)(gq + g + 16) * S_LEN + colb + nt * 8);
                int2 mD = *(const int2*)(mask + (size_t)(gq + g + 24) * S_LEN + colb + nt * 8);
                if (mA.x) l00 += __expf(fabsf(C0[nt][0]));
                if (mA.y) l00 += __expf(fabsf(C0[nt][1]));
                if (mB.x) l01 += __expf(fabsf(C0[nt][2]));
                if (mB.y) l01 += __expf(fabsf(C0[nt][3]));
                if (mC.x) l10 += __expf(fabsf(C1[nt][0]));
                if (mC.y) l10 += __expf(fabsf(C1[nt][1]));
                if (mD.x) l11 += __expf(fabsf(C1[nt][2]));
                if (mD.y) l11 += __expf(fabsf(C1[nt][3]));
            }
        }
    }
    // quad reduce over tig (lanes with same g share rows)
    l00 += __shfl_xor_sync(0xffffffffu, l00, 1); l00 += __shfl_xor_sync(0xffffffffu, l00, 2);
    l01 += __shfl_xor_sync(0xffffffffu, l01, 1); l01 += __shfl_xor_sync(0xffffffffu, l01, 2);
    l10 += __shfl_xor_sync(0xffffffffu, l10, 1); l10 += __shfl_xor_sync(0xffffffffu, l10, 2);
    l11 += __shfl_xor_sync(0xffffffffu, l11, 1); l11 += __shfl_xor_sync(0xffffffffu, l11, 2);
    const float il00 = 1.f / l00, il01 = 1.f / l01;
    const float il10 = 1.f / l10, il11 = 1.f / l11;

    // ================= Pass 2: attn write + O = P @ V =================
    float O0[8][4], O1[8][4];
    #pragma unroll
    for (int nt = 0; nt < 8; ++nt)
        #pragma unroll
        for (int i = 0; i < 4; ++i) { O0[nt][i] = 0.f; O1[nt][i] = 0.f; }

    const size_t abase = (size_t)bh * S_LEN * S_LEN + (size_t)(qtile * QT) * S_LEN;

    for (int kc = 0; kc < NKC; ++kc) {
        const int cf0 = g_mask_flags[fb0 + kc], cf1 = g_mask_flags[fb1 + kc];
        if (cf0 == 0 && cf1 == 0) {
            if (has_attn) {
                float4 z = make_float4(0.f, 0.f, 0.f, 0.f);
                for (int j = tid; j < 2048; j += 128) {
                    int r = j >> 4, c4 = (j & 15) << 2;
                    *(float4*)(attn + abase + (size_t)r * S_LEN + kc * 64 + c4) = z;
                }
            }
            continue;
        }
        __syncthreads();
        {   // K + V chunk fills
            const float* kp = k + bh_qkv + (size_t)kc * 64 * D_DIM;
            const float* vp = v + bh_qkv + (size_t)kc * 64 * D_DIM;
            for (int i = tid; i < 1024; i += 128) {
                int r = i >> 4, c4 = (i & 15) << 2;
                float4 kv = *(const float4*)(kp + (size_t)r * D_DIM + c4);
                *(float4*)(&sK[r * SKS + c4]) = make_float4(
                    __uint_as_float(f2tf32(kv.x)), __uint_as_float(f2tf32(kv.y)),
                    __uint_as_float(f2tf32(kv.z)), __uint_as_float(f2tf32(kv.w)));
                float4 vv = *(const float4*)(vp + (size_t)r * D_DIM + c4);
                *(float4*)(&sV[r * SVS + c4]) = make_float4(
                    __uint_as_float(f2tf32(vv.x)), __uint_as_float(f2tf32(vv.y)),
                    __uint_as_float(f2tf32(vv.z)), __uint_as_float(f2tf32(vv.w)));
            }
        }
        __syncthreads();

        // ---- QK^T recompute ----
        float C0[8][4], C1[8][4];
        #pragma unroll
        for (int nt = 0; nt < 8; ++nt)
            #pragma unroll
            for (int i = 0; i < 4; ++i) { C0[nt][i] = 0.f; C1[nt][i] = 0.f; }
        #pragma unroll
        for (int kt = 0; kt < 8; ++kt)
            #pragma unroll
            for (int nt = 0; nt < 8; ++nt) {
                unsigned b0 = __float_as_uint(sK[(nt * 8 + g) * SKS + kt * 8 + tig]);
                unsigned b1 = __float_as_uint(sK[(nt * 8 + g) * SKS + kt * 8 + tig + 4]);
                mma_tf32(C0[nt], aq[0][kt], b0, b1);
                mma_tf32(C1[nt], aq[1][kt], b0, b1);
            }

        const int wflag = (warp < 2) ? cf0 : cf1;
        // ---- epilogue: p = exp(|s|)*il (masked), write attn + sP ----
        #pragma unroll
        for (int t = 0; t < 2; ++t) {
            float (*C)[4] = t ? C1 : C0;
            const float ilA = t ? il10 : il00, ilB = t ? il11 : il01;
            const int r0 = wrow + t * 16 + g, r1 = r0 + 8;
            float* a0p = has_attn ? attn + abase + (size_t)r0 * S_LEN + kc * 64 : nullptr;
            float* a1p = has_attn ? attn + abase + (size_t)r1 * S_LEN + kc * 64 : nullptr;
            #pragma unroll
            for (int nt = 0; nt < 8; ++nt) {
                float p0, p1, p2, p3;
                if (wflag == 2) {
                    p0 = __expf(fabsf(C[nt][0])) * ilA;
                    p1 = __expf(fabsf(C[nt][1])) * ilA;
                    p2 = __expf(fabsf(C[nt][2])) * ilB;
                    p3 = __expf(fabsf(C[nt][3])) * ilB;
                } else {
                    int colm = kc * 64 + nt * 8 + 2 * tig;
                    int2 m0 = *(const int2*)(mask + (size_t)(qtile * QT + r0) * S_LEN + colm);
                    int2 m1 = *(const int2*)(mask + (size_t)(qtile * QT + r1) * S_LEN + colm);
                    p0 = m0.x ? __expf(fabsf(C[nt][0])) * ilA : 0.f;
                    p1 = m0.y ? __expf(fabsf(C[nt][1])) * ilA : 0.f;
                    p2 = m1.x ? __expf(fabsf(C[nt][2])) * ilB : 0.f;
                    p3 = m1.y ? __expf(fabsf(C[nt][3])) * ilB : 0.f;
                }
                const int colb = nt * 8 + 2 * tig;
                if (has_attn) {
                    *(float2*)(a0p + colb) = make_float2(p0, p1);
                    *(float2*)(a1p + colb) = make_float2(p2, p3);
                }
                *(float2*)(&sP[r0 * SPS + colb]) = make_float2(
                    __uint_as_float(f2tf32(p0)), __uint_as_float(f2tf32(p1)));
                *(float2*)(&sP[r1 * SPS + colb]) = make_float2(
                    __uint_as_float(f2tf32(p2)), __uint_as_float(f2tf32(p3)));
            }
        }
        __syncwarp();   // sP rows are warp-private: write->read within warp only

        // ---- O += P @ V ----
        #pragma unroll
        for (int kt = 0; kt < 8; ++kt) {
            unsigned pa0[4], pa1[4];
            pa0[0] = __float_as_uint(sP[(wrow + g)      * SPS + kt * 8 + tig]);
            pa0[1] = __float_as_uint(sP[(wrow + g + 8)  * SPS + kt * 8 + tig]);
            pa0[2] = __float_as_uint(sP[(wrow + g)      * SPS + kt * 8 + tig + 4]);
            pa0[3] = __float_as_uint(sP[(wrow + g + 8)  * SPS + kt * 8 + tig + 4]);
            pa1[0] = __float_as_uint(sP[(wrow + g + 16) * SPS + kt * 8 + tig]);
            pa1[1] = __float_as_uint(sP[(wrow + g + 24) * SPS + kt * 8 + tig]);
            pa1[2] = __float_as_uint(sP[(wrow + g + 16) * SPS + kt * 8 + tig + 4]);
            pa1[3] = __float_as_uint(sP[(wrow + g + 24) * SPS + kt * 8 + tig + 4]);
            #pragma unroll
            for (int nt = 0; nt < 8; ++nt) {
                unsigned b0 = __float_as_uint(sV[(kt * 8 + tig)     * SVS + nt * 8 + g]);
                unsigned b1 = __float_as_uint(sV[(kt * 8 + tig + 4) * SVS + nt * 8 + g]);
                mma_tf32(O0[nt], pa0, b0, b1);
                mma_tf32(O1[nt], pa1, b0, b1);
            }
        }
    }

    // ================= Output store =================
    #pragma unroll
    for (int t = 0; t < 2; ++t) {
        float (*O)[4] = t ? O1 : O0;
        const int r0 = gq + t * 16 + g;
        float* o0 = out + bh_qkv + (size_t)r0 * D_DIM;
        float* o1 = out + bh_qkv + (size_t)(r0 + 8) * D_DIM;
        #pragma unroll
        for (int nt = 0; nt < 8; ++nt) {
            *(float2*)(o0 + nt * 8 + 2 * tig) = make_float2(O[nt][0], O[nt][1]);
            *(float2*)(o1 + nt * 8 + 2 * tig) = make_float2(O[nt][2], O[nt][3]);
        }
    }
}

extern "C" void kernel_launch(void* const* d_in, const int* in_sizes, int n_in,
                              void* d_out, int out_size) {
    const float* q    = (const float*)d_in[0];
    const float* k    = (const float*)d_in[1];
    const float* v    = (const float*)d_in[2];
    const int*   mask = (const int*)d_in[3];

    float* out = (float*)d_out;
    const long long outN  = (long long)BH * S_LEN * D_DIM;   // 8,388,608
    const long long attnN = (long long)BH * S_LEN * S_LEN;   // 268,435,456
    float* attn = nullptr;
    int has_attn = 0;
    if ((long long)out_size >= outN + attnN) {
        attn = out + outN;
        has_attn = 1;
    }

    static int configured = 0;
    if (!configured) {
        cudaFuncSetAttribute(fused_attn2_kernel,
                             cudaFuncAttributeMaxDynamicSharedMemorySize,
                             SMEM_FLOATS * 4);
        configured = 1;
    }

    mask_flag_kernel<<<32 * 32, 256>>>(mask);
    dim3 grid(NQT, BH);
    fused_attn2_kernel<<<grid, 128, SMEM_FLOATS * 4>>>(q, k, v, mask, out, attn, has_attn);
}